// round 1
// baseline (speedup 1.0000x reference)
#include <cuda_runtime.h>
#include <math.h>

// Problem constants
#define BB 128
#define SS 1024
#define HH 256
#define RR (BB*SS)
#define NEGV 1e9f

// Scratch (device globals; no allocation allowed)
__device__ float g_scores[RR];     // scores_g
__device__ float g_qg[BB*HH];      // q_g
__device__ float g_glimpse[BB*HH]; // glimpse
__device__ float g_qp[BB*HH];      // q_p

// ---------------------------------------------------------------------------
// Kernel: out[b,h] = sum_d in[b,d] * W[h,d]
// grid = B blocks, 256 threads (8 warps). Each warp computes 32 h's via
// coalesced warp dot products.
// inp == nullptr -> use g_glimpse. dst: 0 -> g_qg, 1 -> g_qp.
// ---------------------------------------------------------------------------
__global__ void qmat_kernel(const float* __restrict__ inp,
                            const float* __restrict__ W, int dst) {
    int b = blockIdx.x;
    int tid = threadIdx.x;
    __shared__ float qs[HH];
    const float* src = inp ? inp : g_glimpse;
    qs[tid] = src[b * HH + tid];
    __syncthreads();

    int warp = tid >> 5, lane = tid & 31;
    float* out = dst ? g_qp : g_qg;
    for (int hh = 0; hh < 32; hh++) {
        int h = warp * 32 + hh;
        const float* wrow = W + h * HH;
        float sum = 0.f;
#pragma unroll
        for (int i = 0; i < 8; i++) {
            int d = lane + 32 * i;
            sum += qs[d] * wrow[d];
        }
#pragma unroll
        for (int o = 16; o; o >>= 1) sum += __shfl_xor_sync(0xffffffffu, sum, o);
        if (lane == 0) out[b * HH + h] = sum;
    }
}

// ---------------------------------------------------------------------------
// Fused GEMM + tanh + dot(v) reduce.
// scores[r] = sum_h tanh( (ref[r,:] . W[h,:]) + bias[h] + qv[b,h] ) * v[h]
// Tile: BM=64 rows x all 256 h cols, BK=64, 256 threads (8 warps).
// Warp ty owns rows ty*8..ty*8+7; lane owns cols {lane + 32*j}, j=0..7.
// smem: refS [BK][65] (transposed, padded), wS [BK][257] (transposed, padded).
// If out != nullptr: writes out[r] = score - mask[r]*1e9. Else writes g_scores.
// qsel: 0 -> qv = g_qg, 1 -> qv = g_qp.
// ---------------------------------------------------------------------------
#define BM 64
#define BK 64
#define REFS_STRIDE 65
#define WS_STRIDE 257
#define GEMM_SMEM_BYTES ((BK*REFS_STRIDE + BK*WS_STRIDE) * 4)

extern __shared__ float smem_dyn[];

__global__ __launch_bounds__(256, 2) void gemm_tanh_kernel(
    const float* __restrict__ ref, const float* __restrict__ W,
    const float* __restrict__ bias, const float* __restrict__ v,
    const int* __restrict__ mask, float* __restrict__ out, int qsel)
{
    float* refS = smem_dyn;                      // [BK][65]
    float* wS   = smem_dyn + BK * REFS_STRIDE;   // [BK][257]

    int tid = threadIdx.x;
    int warp = tid >> 5, lane = tid & 31;
    int rbase = blockIdx.x * BM;
    int b = rbase / SS;      // whole 64-row tile lies in one batch (1024 % 64 == 0)

    float acc[8][8];
#pragma unroll
    for (int i = 0; i < 8; i++)
#pragma unroll
        for (int j = 0; j < 8; j++) acc[i][j] = 0.f;

    for (int kk = 0; kk < HH / BK; kk++) {
        int dbase = kk * BK;

        // Load ref tile [64 rows][64 k] -> refS[k][row], coalesced float4 reads.
#pragma unroll
        for (int i = 0; i < 4; i++) {
            int f4 = tid + i * 256;          // 0..1023
            int row = f4 >> 4;
            int g = f4 & 15;
            float4 val = *(const float4*)(ref + (size_t)(rbase + row) * HH + dbase + g * 4);
            refS[(g * 4 + 0) * REFS_STRIDE + row] = val.x;
            refS[(g * 4 + 1) * REFS_STRIDE + row] = val.y;
            refS[(g * 4 + 2) * REFS_STRIDE + row] = val.z;
            refS[(g * 4 + 3) * REFS_STRIDE + row] = val.w;
        }
        // Load W tile [256 h][64 k] -> wS[k][h], coalesced float4 reads.
#pragma unroll
        for (int i = 0; i < 16; i++) {
            int f4 = tid + i * 256;          // 0..4095
            int h = f4 >> 4;
            int g = f4 & 15;
            float4 val = *(const float4*)(W + (size_t)h * HH + dbase + g * 4);
            wS[(g * 4 + 0) * WS_STRIDE + h] = val.x;
            wS[(g * 4 + 1) * WS_STRIDE + h] = val.y;
            wS[(g * 4 + 2) * WS_STRIDE + h] = val.z;
            wS[(g * 4 + 3) * WS_STRIDE + h] = val.w;
        }
        __syncthreads();

#pragma unroll 8
        for (int k = 0; k < BK; k++) {
            float a[8], bb[8];
#pragma unroll
            for (int i = 0; i < 8; i++) a[i] = refS[k * REFS_STRIDE + warp * 8 + i];
#pragma unroll
            for (int j = 0; j < 8; j++) bb[j] = wS[k * WS_STRIDE + lane + 32 * j];
#pragma unroll
            for (int i = 0; i < 8; i++)
#pragma unroll
                for (int j = 0; j < 8; j++) acc[i][j] += a[i] * bb[j];
        }
        __syncthreads();
    }

    // Epilogue: per-column bias + query vector, tanh, dot with v, warp reduce.
    const float* qv = qsel ? g_qp : g_qg;
    float bi[8], vv[8];
#pragma unroll
    for (int j = 0; j < 8; j++) {
        int c = lane + 32 * j;
        bi[j] = bias[c] + qv[b * HH + c];
        vv[j] = v[c];
    }
#pragma unroll
    for (int i = 0; i < 8; i++) {
        float p = 0.f;
#pragma unroll
        for (int j = 0; j < 8; j++) p += tanhf(acc[i][j] + bi[j]) * vv[j];
#pragma unroll
        for (int o = 16; o; o >>= 1) p += __shfl_xor_sync(0xffffffffu, p, o);
        if (lane == 0) {
            int r = rbase + warp * 8 + i;
            if (out) {
                out[r] = p - (float)mask[r] * NEGV;
            } else {
                g_scores[r] = p;
            }
        }
    }
}

// ---------------------------------------------------------------------------
// Masked softmax over S per batch + glimpse = att @ ref + query.
// grid = B blocks, 256 threads. Deterministic tree reductions.
// ---------------------------------------------------------------------------
__global__ void softmax_glimpse_kernel(const float* __restrict__ ref,
                                       const float* __restrict__ query,
                                       const int* __restrict__ mask) {
    int b = blockIdx.x;
    int tid = threadIdx.x;
    __shared__ float e[SS];
    __shared__ float red[256];

    float lm = -INFINITY;
#pragma unroll
    for (int i = 0; i < 4; i++) {
        int s = tid + i * 256;
        float val = g_scores[b * SS + s] - (float)mask[b * SS + s] * NEGV;
        e[s] = val;
        lm = fmaxf(lm, val);
    }
    red[tid] = lm;
    __syncthreads();
    for (int o = 128; o; o >>= 1) {
        if (tid < o) red[tid] = fmaxf(red[tid], red[tid + o]);
        __syncthreads();
    }
    float mx = red[0];
    __syncthreads();

    float ls = 0.f;
#pragma unroll
    for (int i = 0; i < 4; i++) {
        int s = tid + i * 256;
        float ev = expf(e[s] - mx);
        e[s] = ev;
        ls += ev;
    }
    red[tid] = ls;
    __syncthreads();
    for (int o = 128; o; o >>= 1) {
        if (tid < o) red[tid] += red[tid + o];
        __syncthreads();
    }
    float inv = 1.0f / red[0];
    __syncthreads();

    // glimpse[b, d] for d = tid
    int d = tid;
    const float* rb = ref + (size_t)b * SS * HH;
    float acc = 0.f;
#pragma unroll 8
    for (int s = 0; s < SS; s++) {
        acc += e[s] * rb[(size_t)s * HH + d];
    }
    g_glimpse[b * HH + d] = acc * inv + query[b * HH + d];
}

// ---------------------------------------------------------------------------
// Launch
// Input order (metadata): ref, query, mask, wg, bg, wqg, vg, wp, bp, wqp, vp
// ---------------------------------------------------------------------------
extern "C" void kernel_launch(void* const* d_in, const int* in_sizes, int n_in,
                              void* d_out, int out_size) {
    const float* ref   = (const float*)d_in[0];
    const float* query = (const float*)d_in[1];
    const int*   mask  = (const int*)  d_in[2];
    const float* wg    = (const float*)d_in[3];
    const float* bg    = (const float*)d_in[4];
    const float* wqg   = (const float*)d_in[5];
    const float* vg    = (const float*)d_in[6];
    const float* wp    = (const float*)d_in[7];
    const float* bp    = (const float*)d_in[8];
    const float* wqp   = (const float*)d_in[9];
    const float* vp    = (const float*)d_in[10];
    float* out = (float*)d_out;

    cudaFuncSetAttribute(gemm_tanh_kernel,
                         cudaFuncAttributeMaxDynamicSharedMemorySize,
                         GEMM_SMEM_BYTES);

    // 1. q_g = query @ wqg^T
    qmat_kernel<<<BB, 256>>>(query, wqg, 0);
    // 2. scores_g = sum_h tanh(ref@wg^T + bg + q_g) * vg
    gemm_tanh_kernel<<<RR / BM, 256, GEMM_SMEM_BYTES>>>(ref, wg, bg, vg,
                                                        nullptr, nullptr, 0);
    // 3. att = softmax(scores_g - mask*NEG); glimpse = att@ref + query
    softmax_glimpse_kernel<<<BB, 256>>>(ref, query, mask);
    // 4. q_p = glimpse @ wqp^T
    qmat_kernel<<<BB, 256>>>(nullptr, wqp, 1);
    // 5. out = sum_h tanh(ref@wp^T + bp + q_p) * vp  - mask*NEG
    gemm_tanh_kernel<<<RR / BM, 256, GEMM_SMEM_BYTES>>>(ref, wp, bp, vp,
                                                        mask, out, 1);
}

// round 2
// speedup vs baseline: 3.1913x; 3.1913x over previous
#include <cuda_runtime.h>
#include <cuda_bf16.h>
#include <math.h>

// Problem constants
#define BB 128
#define SS 1024
#define HH 256
#define RR (BB*SS)
#define NEGV 1e9f

// Scratch (device globals; no allocation allowed)
__device__ float g_scores[RR];          // scores_g
__device__ float g_qg[BB*HH];           // q_g
__device__ float g_glimpse[BB*HH];      // glimpse
__device__ float g_qp[BB*HH];           // q_p
__device__ __nv_bfloat16 g_wbf[2][HH*HH]; // bf16 copies of wg, wp

__device__ __forceinline__ float fast_tanh(float x) {
    float y;
    asm("tanh.approx.f32 %0, %1;" : "=f"(y) : "f"(x));
    return y;
}

// ---------------------------------------------------------------------------
// Convert wg, wp to bf16 once per launch. 16384 threads, one float4 per matrix.
// ---------------------------------------------------------------------------
__global__ void convert_w_kernel(const float* __restrict__ wg,
                                 const float* __restrict__ wp) {
    int i = blockIdx.x * blockDim.x + threadIdx.x;   // 0..16383 (float4 index)
    float4 a = ((const float4*)wg)[i];
    float4 b = ((const float4*)wp)[i];
    __nv_bfloat162* o0 = (__nv_bfloat162*)&g_wbf[0][i * 4];
    o0[0] = __floats2bfloat162_rn(a.x, a.y);
    o0[1] = __floats2bfloat162_rn(a.z, a.w);
    __nv_bfloat162* o1 = (__nv_bfloat162*)&g_wbf[1][i * 4];
    o1[0] = __floats2bfloat162_rn(b.x, b.y);
    o1[1] = __floats2bfloat162_rn(b.z, b.w);
}

// ---------------------------------------------------------------------------
// q[b,h] = sum_d in[b,d] * W[h,d].  grid (BB, 4): block computes 64 h values.
// ---------------------------------------------------------------------------
__global__ void qmat_kernel(const float* __restrict__ inp,
                            const float* __restrict__ W, int dst) {
    int b = blockIdx.x;
    int tid = threadIdx.x;
    __shared__ float qs[HH];
    const float* src = inp ? inp : g_glimpse;
    qs[tid] = src[b * HH + tid];
    __syncthreads();

    int warp = tid >> 5, lane = tid & 31;
    float* outp = (dst ? g_qp : g_qg) + b * HH;
    int hbase = blockIdx.y * 64 + warp * 8;
#pragma unroll
    for (int hh = 0; hh < 8; hh++) {
        int h = hbase + hh;
        const float* wrow = W + h * HH;
        float s = 0.f;
#pragma unroll
        for (int i = 0; i < 8; i++) s += qs[lane + 32 * i] * wrow[lane + 32 * i];
#pragma unroll
        for (int o = 16; o; o >>= 1) s += __shfl_xor_sync(0xffffffffu, s, o);
        if (lane == 0) outp[h] = s;
    }
}

// ---------------------------------------------------------------------------
// Fused bf16 tensor-core GEMM + tanh + dot(v) reduce.
// scores[r] = sum_h tanh( (ref[r,:] . W[h,:]) + bias[h] + q[b,h] ) * v[h]
// Tile: BM=64 rows x BN=256 (all h), BK=32.  256 threads = 8 warps (2m x 4n).
// Warp (wm, wn): rows wm*32..+31 (2 x m16 tiles), cols wn*64..+63 (8 x n8).
// mma.sync.m16n8k16 bf16->fp32.  ref converted fp32->bf16 in the smem load.
// sel: 0 -> (g_wbf[0], g_qg, write g_scores); 1 -> (g_wbf[1], g_qp, write out).
// ---------------------------------------------------------------------------
#define BM 64
#define BK 32
#define AST 40   // A smem row stride (bf16): 64B row + 16B pad -> conflict-free frags
#define WST 40

__global__ __launch_bounds__(256, 2) void gemm_tanh_mma(
    const float* __restrict__ ref,
    const float* __restrict__ bias, const float* __restrict__ v,
    const int* __restrict__ mask, float* __restrict__ out, int sel)
{
    __shared__ __nv_bfloat16 As[BM * AST];
    __shared__ __nv_bfloat16 Ws[HH * WST];
    __shared__ float red[64][5];

    int tid = threadIdx.x;
    int warp = tid >> 5, lane = tid & 31;
    int wm = warp & 1, wn = warp >> 1;
    int gid = lane >> 2, quad = lane & 3;
    int rbase = blockIdx.x * BM;
    int b = rbase >> 10;  // / SS

    const __nv_bfloat16* Wb = g_wbf[sel];

    float acc[2][8][4];
#pragma unroll
    for (int mt = 0; mt < 2; mt++)
#pragma unroll
        for (int nt = 0; nt < 8; nt++)
#pragma unroll
            for (int k = 0; k < 4; k++) acc[mt][nt][k] = 0.f;

    for (int kk = 0; kk < HH / BK; kk++) {
        // A tile: 64 rows x 32 floats -> bf16.  512 float4 loads, 2 per thread.
#pragma unroll
        for (int i = 0; i < 2; i++) {
            int idx = tid + i * 256;
            int row = idx >> 3, f4 = idx & 7;
            float4 val = *(const float4*)(ref + (size_t)(rbase + row) * HH + kk * BK + f4 * 4);
            *(__nv_bfloat162*)&As[row * AST + f4 * 4]     = __floats2bfloat162_rn(val.x, val.y);
            *(__nv_bfloat162*)&As[row * AST + f4 * 4 + 2] = __floats2bfloat162_rn(val.z, val.w);
        }
        // W tile: 256 rows x 32 bf16 = 1024 x 16B, 4 per thread.
#pragma unroll
        for (int i = 0; i < 4; i++) {
            int idx = tid + i * 256;
            int h = idx >> 2, seg = idx & 3;
            uint4 val = *(const uint4*)(Wb + (size_t)h * HH + kk * BK + seg * 8);
            *(uint4*)&Ws[h * WST + seg * 8] = val;
        }
        __syncthreads();

#pragma unroll
        for (int ks = 0; ks < 2; ks++) {
            unsigned a[2][4];
#pragma unroll
            for (int mt = 0; mt < 2; mt++) {
                const __nv_bfloat16* base = As + (wm * 32 + mt * 16 + gid) * AST + ks * 16 + quad * 2;
                a[mt][0] = *(const unsigned*)(base);
                a[mt][1] = *(const unsigned*)(base + 8 * AST);
                a[mt][2] = *(const unsigned*)(base + 8);
                a[mt][3] = *(const unsigned*)(base + 8 * AST + 8);
            }
#pragma unroll
            for (int nt = 0; nt < 8; nt++) {
                const __nv_bfloat16* bb = Ws + (wn * 64 + nt * 8 + gid) * WST + ks * 16 + quad * 2;
                unsigned b0 = *(const unsigned*)(bb);
                unsigned b1 = *(const unsigned*)(bb + 8);
#pragma unroll
                for (int mt = 0; mt < 2; mt++) {
                    asm volatile(
                        "mma.sync.aligned.m16n8k16.row.col.f32.bf16.bf16.f32 "
                        "{%0,%1,%2,%3}, {%4,%5,%6,%7}, {%8,%9}, {%0,%1,%2,%3};"
                        : "+f"(acc[mt][nt][0]), "+f"(acc[mt][nt][1]),
                          "+f"(acc[mt][nt][2]), "+f"(acc[mt][nt][3])
                        : "r"(a[mt][0]), "r"(a[mt][1]), "r"(a[mt][2]), "r"(a[mt][3]),
                          "r"(b0), "r"(b1));
                }
            }
        }
        __syncthreads();
    }

    // Epilogue: load bias+q+v for this thread's 16 columns (deferred to keep
    // mainloop register pressure low), tanh, dot v, reduce.
    const float* q = (sel ? g_qp : g_qg) + b * HH;
    float bq[8][2], vv[8][2];
#pragma unroll
    for (int nt = 0; nt < 8; nt++) {
        int c = wn * 64 + nt * 8 + quad * 2;
        bq[nt][0] = bias[c] + q[c];
        bq[nt][1] = bias[c + 1] + q[c + 1];
        vv[nt][0] = v[c];
        vv[nt][1] = v[c + 1];
    }

#pragma unroll
    for (int mt = 0; mt < 2; mt++) {
        float lo = 0.f, hi = 0.f;
#pragma unroll
        for (int nt = 0; nt < 8; nt++) {
            lo += fast_tanh(acc[mt][nt][0] + bq[nt][0]) * vv[nt][0];
            lo += fast_tanh(acc[mt][nt][1] + bq[nt][1]) * vv[nt][1];
            hi += fast_tanh(acc[mt][nt][2] + bq[nt][0]) * vv[nt][0];
            hi += fast_tanh(acc[mt][nt][3] + bq[nt][1]) * vv[nt][1];
        }
        lo += __shfl_xor_sync(0xffffffffu, lo, 1);
        lo += __shfl_xor_sync(0xffffffffu, lo, 2);
        hi += __shfl_xor_sync(0xffffffffu, hi, 1);
        hi += __shfl_xor_sync(0xffffffffu, hi, 2);
        if (quad == 0) {
            red[wm * 32 + mt * 16 + gid][wn]     = lo;
            red[wm * 32 + mt * 16 + gid + 8][wn] = hi;
        }
    }
    __syncthreads();

    if (tid < 64) {
        float t = red[tid][0] + red[tid][1] + red[tid][2] + red[tid][3];
        int r = rbase + tid;
        if (out) out[r] = t - (float)mask[r] * NEGV;
        else     g_scores[r] = t;
    }
}

// ---------------------------------------------------------------------------
// Masked softmax over S per batch + glimpse = att @ ref + query.
// ---------------------------------------------------------------------------
__global__ void softmax_glimpse_kernel(const float* __restrict__ ref,
                                       const float* __restrict__ query,
                                       const int* __restrict__ mask) {
    int b = blockIdx.x;
    int tid = threadIdx.x;
    __shared__ float e[SS];
    __shared__ float red[256];

    float lm = -INFINITY;
#pragma unroll
    for (int i = 0; i < 4; i++) {
        int s = tid + i * 256;
        float val = g_scores[b * SS + s] - (float)mask[b * SS + s] * NEGV;
        e[s] = val;
        lm = fmaxf(lm, val);
    }
    red[tid] = lm;
    __syncthreads();
    for (int o = 128; o; o >>= 1) {
        if (tid < o) red[tid] = fmaxf(red[tid], red[tid + o]);
        __syncthreads();
    }
    float mx = red[0];
    __syncthreads();

    float ls = 0.f;
#pragma unroll
    for (int i = 0; i < 4; i++) {
        int s = tid + i * 256;
        float ev = expf(e[s] - mx);
        e[s] = ev;
        ls += ev;
    }
    red[tid] = ls;
    __syncthreads();
    for (int o = 128; o; o >>= 1) {
        if (tid < o) red[tid] += red[tid + o];
        __syncthreads();
    }
    float inv = 1.0f / red[0];
    __syncthreads();

    // glimpse[b, d], d = tid, 4-way ILP over s
    int d = tid;
    const float* rb = ref + (size_t)b * SS * HH;
    float a0 = 0.f, a1 = 0.f, a2 = 0.f, a3 = 0.f;
#pragma unroll 2
    for (int s = 0; s < SS; s += 4) {
        a0 += e[s]     * rb[(size_t)(s)     * HH + d];
        a1 += e[s + 1] * rb[(size_t)(s + 1) * HH + d];
        a2 += e[s + 2] * rb[(size_t)(s + 2) * HH + d];
        a3 += e[s + 3] * rb[(size_t)(s + 3) * HH + d];
    }
    float acc = (a0 + a1) + (a2 + a3);
    g_glimpse[b * HH + d] = acc * inv + query[b * HH + d];
}

// ---------------------------------------------------------------------------
// Launch. Input order: ref, query, mask, wg, bg, wqg, vg, wp, bp, wqp, vp
// ---------------------------------------------------------------------------
extern "C" void kernel_launch(void* const* d_in, const int* in_sizes, int n_in,
                              void* d_out, int out_size) {
    const float* ref   = (const float*)d_in[0];
    const float* query = (const float*)d_in[1];
    const int*   mask  = (const int*)  d_in[2];
    const float* wg    = (const float*)d_in[3];
    const float* bg    = (const float*)d_in[4];
    const float* wqg   = (const float*)d_in[5];
    const float* vg    = (const float*)d_in[6];
    const float* wp    = (const float*)d_in[7];
    const float* bp    = (const float*)d_in[8];
    const float* wqp   = (const float*)d_in[9];
    const float* vp    = (const float*)d_in[10];
    float* out = (float*)d_out;

    // 0. bf16 copies of wg, wp
    convert_w_kernel<<<64, 256>>>(wg, wp);
    // 1. q_g = query @ wqg^T
    qmat_kernel<<<dim3(BB, 4), 256>>>(query, wqg, 0);
    // 2. scores_g
    gemm_tanh_mma<<<RR / BM, 256>>>(ref, bg, vg, mask, nullptr, 0);
    // 3. softmax + glimpse
    softmax_glimpse_kernel<<<BB, 256>>>(ref, query, mask);
    // 4. q_p = glimpse @ wqp^T
    qmat_kernel<<<dim3(BB, 4), 256>>>(nullptr, wqp, 1);
    // 5. out
    gemm_tanh_mma<<<RR / BM, 256>>>(ref, bp, vp, mask, out, 1);
}

// round 4
// speedup vs baseline: 4.0943x; 1.2829x over previous
#include <cuda_runtime.h>
#include <cuda_bf16.h>
#include <math.h>

// Problem constants
#define BB 128
#define SS 1024
#define HH 256
#define RR (BB*SS)
#define NEGV 1e9f
#define NSPLIT 8
#define SCHUNK (SS/NSPLIT)   // 128

// Scratch (device globals; no allocation allowed)
__device__ float g_scores[RR];            // scores_g
__device__ float g_e[RR];                 // exp(scores - max)
__device__ float g_inv[BB];               // 1/sum
__device__ float g_part[BB][NSPLIT][HH];  // glimpse partials
__device__ float g_qg[BB*HH];             // q_g
__device__ float g_glimpse[BB*HH];        // glimpse
__device__ float g_qp[BB*HH];             // q_p
__device__ __nv_bfloat16 g_wbf[2][HH*HH]; // bf16 copies of wg, wp

__device__ __forceinline__ float fast_tanh(float x) {
    float y;
    asm("tanh.approx.f32 %0, %1;" : "=f"(y) : "f"(x));
    return y;
}

__device__ __forceinline__ unsigned smem_u32(const void* p) {
    return (unsigned)__cvta_generic_to_shared(p);
}
#define CP_ASYNC16(dst, src) \
    asm volatile("cp.async.cg.shared.global [%0], [%1], 16;" :: "r"(dst), "l"(src))
#define CP_COMMIT() asm volatile("cp.async.commit_group;")
#define CP_WAIT0()  asm volatile("cp.async.wait_group 0;" ::: "memory")

// ---------------------------------------------------------------------------
// Convert wg, wp to bf16 once per launch.
// ---------------------------------------------------------------------------
__global__ void convert_w_kernel(const float* __restrict__ wg,
                                 const float* __restrict__ wp) {
    int i = blockIdx.x * blockDim.x + threadIdx.x;   // float4 index
    float4 a = ((const float4*)wg)[i];
    float4 b = ((const float4*)wp)[i];
    __nv_bfloat162* o0 = (__nv_bfloat162*)&g_wbf[0][i * 4];
    o0[0] = __floats2bfloat162_rn(a.x, a.y);
    o0[1] = __floats2bfloat162_rn(a.z, a.w);
    __nv_bfloat162* o1 = (__nv_bfloat162*)&g_wbf[1][i * 4];
    o1[0] = __floats2bfloat162_rn(b.x, b.y);
    o1[1] = __floats2bfloat162_rn(b.z, b.w);
}

// ---------------------------------------------------------------------------
// q[b,h] = sum_d in[b,d] * W[h,d].  grid (BB, 4): block computes 64 h values.
// ---------------------------------------------------------------------------
__global__ void qmat_kernel(const float* __restrict__ inp,
                            const float* __restrict__ W, int dst) {
    int b = blockIdx.x;
    int tid = threadIdx.x;
    __shared__ float qs[HH];
    const float* src = inp ? inp : g_glimpse;
    qs[tid] = src[b * HH + tid];
    __syncthreads();

    int warp = tid >> 5, lane = tid & 31;
    float* outp = (dst ? g_qp : g_qg) + b * HH;
    int hbase = blockIdx.y * 64 + warp * 8;
#pragma unroll
    for (int hh = 0; hh < 8; hh++) {
        int h = hbase + hh;
        const float* wrow = W + h * HH;
        float s = 0.f;
#pragma unroll
        for (int i = 0; i < 8; i++) s += qs[lane + 32 * i] * wrow[lane + 32 * i];
#pragma unroll
        for (int o = 16; o; o >>= 1) s += __shfl_xor_sync(0xffffffffu, s, o);
        if (lane == 0) outp[h] = s;
    }
}

// ---------------------------------------------------------------------------
// Fused bf16 tensor-core GEMM + tanh + dot(v) reduce, double-buffered.
// Tile: BM=64 rows x BN=256 (all h), BK=32.  256 threads = 8 warps (2m x 4n).
// W loaded via cp.async (bf16 raw); A (ref) register-staged fp32->bf16.
// ---------------------------------------------------------------------------
#define BM 64
#define BK 32
#define AST 40   // smem row strides (bf16 elems), 16B pad -> conflict-free
#define WST 40
#define A_ELEMS (BM*AST)     // 2560
#define W_ELEMS (HH*WST)     // 10240
#define GEMM_DSMEM ((A_ELEMS + W_ELEMS) * 2 * 2)  // two buffers, bf16

extern __shared__ __nv_bfloat16 dyn_smem[];

__global__ __launch_bounds__(256, 2) void gemm_tanh_mma(
    const float* __restrict__ ref,
    const float* __restrict__ bias, const float* __restrict__ v,
    const int* __restrict__ mask, float* __restrict__ out, int sel)
{
    __nv_bfloat16* Abuf[2] = { dyn_smem, dyn_smem + A_ELEMS };
    __nv_bfloat16* Wbuf[2] = { dyn_smem + 2 * A_ELEMS,
                               dyn_smem + 2 * A_ELEMS + W_ELEMS };
    __shared__ float red[64][5];

    int tid = threadIdx.x;
    int warp = tid >> 5, lane = tid & 31;
    int wm = warp & 1, wn = warp >> 1;
    int gid = lane >> 2, quad = lane & 3;
    int rbase = blockIdx.x * BM;
    int b = rbase >> 10;

    const __nv_bfloat16* Wb = g_wbf[sel];

    // Per-thread fixed load coordinates
    int arow0 = tid >> 3,            af4_0 = tid & 7;            // i=0
    int arow1 = (tid + 256) >> 3,    af4_1 = tid & 7;            // i=1
    const float* aptr0 = ref + (size_t)(rbase + arow0) * HH + af4_0 * 4;
    const float* aptr1 = ref + (size_t)(rbase + arow1) * HH + af4_1 * 4;
    unsigned asm0 = 0, asm1 = 0;  // smem byte offsets computed per buffer below
    int aoff0 = arow0 * AST + af4_0 * 4;
    int aoff1 = arow1 * AST + af4_1 * 4;

    float acc[2][8][4];
#pragma unroll
    for (int mt = 0; mt < 2; mt++)
#pragma unroll
        for (int nt = 0; nt < 8; nt++)
#pragma unroll
            for (int k = 0; k < 4; k++) acc[mt][nt][k] = 0.f;

    // ---- preload kk = 0 into buffer 0 ----
    {
#pragma unroll
        for (int i = 0; i < 4; i++) {
            int idx = tid + i * 256;
            int h = idx >> 2, seg = idx & 3;
            CP_ASYNC16(smem_u32(Wbuf[0] + h * WST + seg * 8),
                       Wb + (size_t)h * HH + seg * 8);
        }
        CP_COMMIT();
        float4 v0 = *(const float4*)(aptr0);
        float4 v1 = *(const float4*)(aptr1);
        *(__nv_bfloat162*)&Abuf[0][aoff0]     = __floats2bfloat162_rn(v0.x, v0.y);
        *(__nv_bfloat162*)&Abuf[0][aoff0 + 2] = __floats2bfloat162_rn(v0.z, v0.w);
        *(__nv_bfloat162*)&Abuf[0][aoff1]     = __floats2bfloat162_rn(v1.x, v1.y);
        *(__nv_bfloat162*)&Abuf[0][aoff1 + 2] = __floats2bfloat162_rn(v1.z, v1.w);
        CP_WAIT0();
    }
    __syncthreads();

    for (int kk = 0; kk < HH / BK; kk++) {
        int cur = kk & 1, nxt = cur ^ 1;
        float4 v0, v1;
        if (kk < HH / BK - 1) {
            int dnext = (kk + 1) * BK;
            // issue W cp.async into next buffer
#pragma unroll
            for (int i = 0; i < 4; i++) {
                int idx = tid + i * 256;
                int h = idx >> 2, seg = idx & 3;
                CP_ASYNC16(smem_u32(Wbuf[nxt] + h * WST + seg * 8),
                           Wb + (size_t)h * HH + dnext + seg * 8);
            }
            CP_COMMIT();
            v0 = *(const float4*)(aptr0 + dnext);
            v1 = *(const float4*)(aptr1 + dnext);
        }

        // compute on current buffer
        const __nv_bfloat16* As = Abuf[cur];
        const __nv_bfloat16* Ws = Wbuf[cur];
#pragma unroll
        for (int ks = 0; ks < 2; ks++) {
            unsigned a[2][4];
#pragma unroll
            for (int mt = 0; mt < 2; mt++) {
                const __nv_bfloat16* base = As + (wm * 32 + mt * 16 + gid) * AST + ks * 16 + quad * 2;
                a[mt][0] = *(const unsigned*)(base);
                a[mt][1] = *(const unsigned*)(base + 8 * AST);
                a[mt][2] = *(const unsigned*)(base + 8);
                a[mt][3] = *(const unsigned*)(base + 8 * AST + 8);
            }
#pragma unroll
            for (int nt = 0; nt < 8; nt++) {
                const __nv_bfloat16* bbp = Ws + (wn * 64 + nt * 8 + gid) * WST + ks * 16 + quad * 2;
                unsigned b0 = *(const unsigned*)(bbp);
                unsigned b1 = *(const unsigned*)(bbp + 8);
#pragma unroll
                for (int mt = 0; mt < 2; mt++) {
                    asm volatile(
                        "mma.sync.aligned.m16n8k16.row.col.f32.bf16.bf16.f32 "
                        "{%0,%1,%2,%3}, {%4,%5,%6,%7}, {%8,%9}, {%0,%1,%2,%3};"
                        : "+f"(acc[mt][nt][0]), "+f"(acc[mt][nt][1]),
                          "+f"(acc[mt][nt][2]), "+f"(acc[mt][nt][3])
                        : "r"(a[mt][0]), "r"(a[mt][1]), "r"(a[mt][2]), "r"(a[mt][3]),
                          "r"(b0), "r"(b1));
                }
            }
        }

        if (kk < HH / BK - 1) {
            *(__nv_bfloat162*)&Abuf[nxt][aoff0]     = __floats2bfloat162_rn(v0.x, v0.y);
            *(__nv_bfloat162*)&Abuf[nxt][aoff0 + 2] = __floats2bfloat162_rn(v0.z, v0.w);
            *(__nv_bfloat162*)&Abuf[nxt][aoff1]     = __floats2bfloat162_rn(v1.x, v1.y);
            *(__nv_bfloat162*)&Abuf[nxt][aoff1 + 2] = __floats2bfloat162_rn(v1.z, v1.w);
            CP_WAIT0();
            __syncthreads();
        }
    }

    // Epilogue
    const float* q = (sel ? g_qp : g_qg) + b * HH;
    float bq[8][2], vv[8][2];
#pragma unroll
    for (int nt = 0; nt < 8; nt++) {
        int c = wn * 64 + nt * 8 + quad * 2;
        bq[nt][0] = bias[c] + q[c];
        bq[nt][1] = bias[c + 1] + q[c + 1];
        vv[nt][0] = v[c];
        vv[nt][1] = v[c + 1];
    }

#pragma unroll
    for (int mt = 0; mt < 2; mt++) {
        float lo = 0.f, hi = 0.f;
#pragma unroll
        for (int nt = 0; nt < 8; nt++) {
            lo += fast_tanh(acc[mt][nt][0] + bq[nt][0]) * vv[nt][0];
            lo += fast_tanh(acc[mt][nt][1] + bq[nt][1]) * vv[nt][1];
            hi += fast_tanh(acc[mt][nt][2] + bq[nt][0]) * vv[nt][0];
            hi += fast_tanh(acc[mt][nt][3] + bq[nt][1]) * vv[nt][1];
        }
        lo += __shfl_xor_sync(0xffffffffu, lo, 1);
        lo += __shfl_xor_sync(0xffffffffu, lo, 2);
        hi += __shfl_xor_sync(0xffffffffu, hi, 1);
        hi += __shfl_xor_sync(0xffffffffu, hi, 2);
        if (quad == 0) {
            red[wm * 32 + mt * 16 + gid][wn]     = lo;
            red[wm * 32 + mt * 16 + gid + 8][wn] = hi;
        }
    }
    __syncthreads();

    if (tid < 64) {
        float t = red[tid][0] + red[tid][1] + red[tid][2] + red[tid][3];
        int r = rbase + tid;
        if (out) out[r] = t - (float)mask[r] * NEGV;
        else     g_scores[r] = t;
    }
}

// ---------------------------------------------------------------------------
// Softmax prep: per batch, masked max + exp + sum.  Writes g_e, g_inv.
// ---------------------------------------------------------------------------
__global__ void softmax_prep_kernel(const int* __restrict__ mask) {
    int b = blockIdx.x;
    int tid = threadIdx.x;
    __shared__ float e[SS];
    __shared__ float red[256];

    float lm = -INFINITY;
#pragma unroll
    for (int i = 0; i < 4; i++) {
        int s = tid + i * 256;
        float val = g_scores[b * SS + s] - (float)mask[b * SS + s] * NEGV;
        e[s] = val;
        lm = fmaxf(lm, val);
    }
    red[tid] = lm;
    __syncthreads();
    for (int o = 128; o; o >>= 1) {
        if (tid < o) red[tid] = fmaxf(red[tid], red[tid + o]);
        __syncthreads();
    }
    float mx = red[0];
    __syncthreads();

    float ls = 0.f;
#pragma unroll
    for (int i = 0; i < 4; i++) {
        int s = tid + i * 256;
        float ev = expf(e[s] - mx);
        g_e[b * SS + s] = ev;
        ls += ev;
    }
    red[tid] = ls;
    __syncthreads();
    for (int o = 128; o; o >>= 1) {
        if (tid < o) red[tid] += red[tid + o];
        __syncthreads();
    }
    if (tid == 0) g_inv[b] = 1.0f / red[0];
}

// ---------------------------------------------------------------------------
// Glimpse partial: grid (NSPLIT, BB).  Block reduces SCHUNK s-rows.
// ---------------------------------------------------------------------------
__global__ void glimpse_partial_kernel(const float* __restrict__ ref) {
    int split = blockIdx.x, b = blockIdx.y;
    int tid = threadIdx.x;
    int s0 = split * SCHUNK;
    __shared__ float es[SCHUNK];
    if (tid < SCHUNK) es[tid] = g_e[b * SS + s0 + tid];
    __syncthreads();

    const float* rb = ref + ((size_t)b * SS + s0) * HH;
    int d = tid;
    float a0 = 0.f, a1 = 0.f, a2 = 0.f, a3 = 0.f;
#pragma unroll 4
    for (int s = 0; s < SCHUNK; s += 4) {
        a0 += es[s]     * rb[(size_t)(s)     * HH + d];
        a1 += es[s + 1] * rb[(size_t)(s + 1) * HH + d];
        a2 += es[s + 2] * rb[(size_t)(s + 2) * HH + d];
        a3 += es[s + 3] * rb[(size_t)(s + 3) * HH + d];
    }
    g_part[b][split][d] = (a0 + a1) + (a2 + a3);
}

// ---------------------------------------------------------------------------
// Glimpse combine: sum partials * inv + query.
// ---------------------------------------------------------------------------
__global__ void glimpse_combine_kernel(const float* __restrict__ query) {
    int b = blockIdx.x;
    int d = threadIdx.x;
    float s = 0.f;
#pragma unroll
    for (int p = 0; p < NSPLIT; p++) s += g_part[b][p][d];
    g_glimpse[b * HH + d] = s * g_inv[b] + query[b * HH + d];
}

// ---------------------------------------------------------------------------
// Launch. Input order: ref, query, mask, wg, bg, wqg, vg, wp, bp, wqp, vp
// ---------------------------------------------------------------------------
extern "C" void kernel_launch(void* const* d_in, const int* in_sizes, int n_in,
                              void* d_out, int out_size) {
    const float* ref   = (const float*)d_in[0];
    const float* query = (const float*)d_in[1];
    const int*   mask  = (const int*)  d_in[2];
    const float* wg    = (const float*)d_in[3];
    const float* bg    = (const float*)d_in[4];
    const float* wqg   = (const float*)d_in[5];
    const float* vg    = (const float*)d_in[6];
    const float* wp    = (const float*)d_in[7];
    const float* bp    = (const float*)d_in[8];
    const float* wqp   = (const float*)d_in[9];
    const float* vp    = (const float*)d_in[10];
    float* out = (float*)d_out;

    cudaFuncSetAttribute(gemm_tanh_mma,
                         cudaFuncAttributeMaxDynamicSharedMemorySize,
                         GEMM_DSMEM);

    convert_w_kernel<<<64, 256>>>(wg, wp);
    qmat_kernel<<<dim3(BB, 4), 256>>>(query, wqg, 0);
    gemm_tanh_mma<<<RR / BM, 256, GEMM_DSMEM>>>(ref, bg, vg, mask, nullptr, 0);
    softmax_prep_kernel<<<BB, 256>>>(mask);
    glimpse_partial_kernel<<<dim3(NSPLIT, BB), 256>>>(ref);
    glimpse_combine_kernel<<<BB, HH>>>(query);
    qmat_kernel<<<dim3(BB, 4), 256>>>(nullptr, wqp, 1);
    gemm_tanh_mma<<<RR / BM, 256, GEMM_DSMEM>>>(ref, bp, vp, mask, out, 1);
}

// round 10
// speedup vs baseline: 4.5138x; 1.1025x over previous
#include <cuda_runtime.h>
#include <cuda_bf16.h>
#include <math.h>
#include <stdint.h>

// Problem constants
#define BB 128
#define SS 1024
#define HH 256
#define RR (BB*SS)
#define NEGV 1e9f
#define NSPLIT 16
#define SCHUNK (SS/NSPLIT)   // 64

// Scratch (device globals; no allocation allowed)
__device__ float g_scores[RR];
__device__ float g_e[RR];
__device__ float g_inv[BB];
__device__ float g_part[BB][NSPLIT][HH];
__device__ float g_qg[BB*HH];
__device__ float g_glimpse[BB*HH];
__device__ float g_qp[BB*HH];
__device__ unsigned char g_w8[2][HH*HH];   // e4m3 copies of wg, wp

__device__ __forceinline__ float fast_tanh(float x) {
    float y;
    asm("tanh.approx.f32 %0, %1;" : "=f"(y) : "f"(x));
    return y;
}
__device__ __forceinline__ unsigned smem_u32(const void* p) {
    return (unsigned)__cvta_generic_to_shared(p);
}
#define CP_ASYNC16(dst, src) \
    asm volatile("cp.async.cg.shared.global [%0], [%1], 16;" :: "r"(dst), "l"(src))
#define CP_COMMIT() asm volatile("cp.async.commit_group;")
#define CP_WAIT0()  asm volatile("cp.async.wait_group 0;" ::: "memory")

// Pack 4 consecutive floats (k order) into 4 e4m3 bytes (byte0 = first k).
// cvt.rn.satfinite.e4m3x2.f32 d(.b16), a, b  packs {b:lo, a:hi}.
__device__ __forceinline__ unsigned pack_e4m3x4(float f0, float f1, float f2, float f3) {
    unsigned short lo, hi;
    asm("cvt.rn.satfinite.e4m3x2.f32 %0, %1, %2;" : "=h"(lo) : "f"(f1), "f"(f0));
    asm("cvt.rn.satfinite.e4m3x2.f32 %0, %1, %2;" : "=h"(hi) : "f"(f3), "f"(f2));
    return (unsigned)lo | ((unsigned)hi << 16);
}

// ---------------------------------------------------------------------------
// Convert wg, wp to e4m3 once per launch. float4 -> 4 bytes per thread.
// ---------------------------------------------------------------------------
__global__ void convert_w_kernel(const float* __restrict__ wg,
                                 const float* __restrict__ wp) {
    int i = blockIdx.x * blockDim.x + threadIdx.x;   // float4 index
    float4 a = ((const float4*)wg)[i];
    float4 b = ((const float4*)wp)[i];
    ((unsigned*)g_w8[0])[i] = pack_e4m3x4(a.x, a.y, a.z, a.w);
    ((unsigned*)g_w8[1])[i] = pack_e4m3x4(b.x, b.y, b.z, b.w);
}

// ---------------------------------------------------------------------------
// q[b,h] = sum_d in[b,d] * W[h,d]  (fp32, tiny).
// ---------------------------------------------------------------------------
__global__ void qmat_kernel(const float* __restrict__ inp,
                            const float* __restrict__ W, int dst) {
    int b = blockIdx.x;
    int tid = threadIdx.x;
    __shared__ float qs[HH];
    const float* src = inp ? inp : g_glimpse;
    qs[tid] = src[b * HH + tid];
    __syncthreads();

    int warp = tid >> 5, lane = tid & 31;
    float* outp = (dst ? g_qp : g_qg) + b * HH;
    int hbase = blockIdx.y * 64 + warp * 8;
#pragma unroll
    for (int hh = 0; hh < 8; hh++) {
        int h = hbase + hh;
        const float* wrow = W + h * HH;
        float s = 0.f;
#pragma unroll
        for (int i = 0; i < 8; i++) s += qs[lane + 32 * i] * wrow[lane + 32 * i];
#pragma unroll
        for (int o = 16; o; o >>= 1) s += __shfl_xor_sync(0xffffffffu, s, o);
        if (lane == 0) outp[h] = s;
    }
}

// ---------------------------------------------------------------------------
// Fused FP8 tensor-core GEMM + tanh + dot(v) reduce, double-buffered.
// scores[r] = sum_h tanh( (ref[r,:] . W[h,:]) + bias[h] + q[b,h] ) * v[h]
// Tile BM=64 x BN=256 (all h), BK=64 bytes.  256 threads = 8 warps (2m x 4n).
// mma.sync.m16n8k32.f32.e4m3.e4m3.f32; ref converted fp32->e4m3 in registers.
// ---------------------------------------------------------------------------
#define BM 64
#define BKB 64              // K elements (bytes) per chunk
#define NCH (HH/BKB)        // 4
#define WSTB 80             // smem byte stride per row (64 + 16 pad)
#define A_BYTES (BM*WSTB)   // 5120
#define W_BYTES (HH*WSTB)   // 20480
#define GEMM_DSMEM (2*(A_BYTES + W_BYTES))   // 51200

extern __shared__ unsigned char dyn8[];

__global__ __launch_bounds__(256, 2) void gemm_tanh_mma(
    const float* __restrict__ ref,
    const float* __restrict__ bias, const float* __restrict__ v,
    const int* __restrict__ mask, float* __restrict__ out, int sel)
{
    unsigned char* Ab[2] = { dyn8, dyn8 + A_BYTES };
    unsigned char* Wb[2] = { dyn8 + 2*A_BYTES, dyn8 + 2*A_BYTES + W_BYTES };
    __shared__ float red[64][5];

    int tid = threadIdx.x;
    int warp = tid >> 5, lane = tid & 31;
    int wm = warp & 1, wn = warp >> 1;
    int gid = lane >> 2, quad = lane & 3;
    int rbase = blockIdx.x * BM;
    int b = rbase >> 10;

    const unsigned char* W8 = g_w8[sel];

    // Per-thread A load coords: one 16-byte k-segment of one row.
    int arow = tid >> 2, aseg = tid & 3;
    const float* aptr = ref + (size_t)(rbase + arow) * HH + aseg * 16;
    int aoff = arow * WSTB + aseg * 16;

    float acc[2][8][4];
#pragma unroll
    for (int mt = 0; mt < 2; mt++)
#pragma unroll
        for (int nt = 0; nt < 8; nt++)
#pragma unroll
            for (int k = 0; k < 4; k++) acc[mt][nt][k] = 0.f;

    // ---- preload chunk 0 into buffer 0 ----
    {
#pragma unroll
        for (int i = 0; i < 4; i++) {
            int u = tid + i * 256;
            int row = u >> 2, seg = u & 3;
            CP_ASYNC16(smem_u32(Wb[0] + row * WSTB + seg * 16),
                       W8 + (size_t)row * HH + seg * 16);
        }
        CP_COMMIT();
        float4 p0 = *(const float4*)(aptr);
        float4 p1 = *(const float4*)(aptr + 4);
        float4 p2 = *(const float4*)(aptr + 8);
        float4 p3 = *(const float4*)(aptr + 12);
        uint4 aval;
        aval.x = pack_e4m3x4(p0.x, p0.y, p0.z, p0.w);
        aval.y = pack_e4m3x4(p1.x, p1.y, p1.z, p1.w);
        aval.z = pack_e4m3x4(p2.x, p2.y, p2.z, p2.w);
        aval.w = pack_e4m3x4(p3.x, p3.y, p3.z, p3.w);
        *(uint4*)(Ab[0] + aoff) = aval;
        CP_WAIT0();
    }
    __syncthreads();

    for (int c = 0; c < NCH; c++) {
        int cur = c & 1, nxt = cur ^ 1;
        uint4 aval;
        if (c < NCH - 1) {
            int knext = (c + 1) * BKB;
#pragma unroll
            for (int i = 0; i < 4; i++) {
                int u = tid + i * 256;
                int row = u >> 2, seg = u & 3;
                CP_ASYNC16(smem_u32(Wb[nxt] + row * WSTB + seg * 16),
                           W8 + (size_t)row * HH + knext + seg * 16);
            }
            CP_COMMIT();
            float4 p0 = *(const float4*)(aptr + knext);
            float4 p1 = *(const float4*)(aptr + knext + 4);
            float4 p2 = *(const float4*)(aptr + knext + 8);
            float4 p3 = *(const float4*)(aptr + knext + 12);
            aval.x = pack_e4m3x4(p0.x, p0.y, p0.z, p0.w);
            aval.y = pack_e4m3x4(p1.x, p1.y, p1.z, p1.w);
            aval.z = pack_e4m3x4(p2.x, p2.y, p2.z, p2.w);
            aval.w = pack_e4m3x4(p3.x, p3.y, p3.z, p3.w);
        }

        // compute on current buffer: 2 k32 steps
        const unsigned char* As = Ab[cur];
        const unsigned char* Ws = Wb[cur];
#pragma unroll
        for (int ks = 0; ks < 2; ks++) {
            unsigned a[2][4];
#pragma unroll
            for (int mt = 0; mt < 2; mt++) {
                const unsigned char* base = As + (wm * 32 + mt * 16 + gid) * WSTB + ks * 32 + quad * 4;
                a[mt][0] = *(const unsigned*)(base);
                a[mt][1] = *(const unsigned*)(base + 8 * WSTB);
                a[mt][2] = *(const unsigned*)(base + 16);
                a[mt][3] = *(const unsigned*)(base + 8 * WSTB + 16);
            }
#pragma unroll
            for (int nt = 0; nt < 8; nt++) {
                const unsigned char* bbp = Ws + (wn * 64 + nt * 8 + gid) * WSTB + ks * 32 + quad * 4;
                unsigned b0 = *(const unsigned*)(bbp);
                unsigned b1 = *(const unsigned*)(bbp + 16);
#pragma unroll
                for (int mt = 0; mt < 2; mt++) {
                    asm volatile(
                        "mma.sync.aligned.m16n8k32.row.col.f32.e4m3.e4m3.f32 "
                        "{%0,%1,%2,%3}, {%4,%5,%6,%7}, {%8,%9}, {%0,%1,%2,%3};"
                        : "+f"(acc[mt][nt][0]), "+f"(acc[mt][nt][1]),
                          "+f"(acc[mt][nt][2]), "+f"(acc[mt][nt][3])
                        : "r"(a[mt][0]), "r"(a[mt][1]), "r"(a[mt][2]), "r"(a[mt][3]),
                          "r"(b0), "r"(b1));
                }
            }
        }

        if (c < NCH - 1) {
            *(uint4*)(Ab[nxt] + aoff) = aval;
            CP_WAIT0();
            __syncthreads();
        }
    }

    // Epilogue: bias + q, tanh, dot v, reduce.
    const float* q = (sel ? g_qp : g_qg) + b * HH;
    float bq[8][2], vv[8][2];
#pragma unroll
    for (int nt = 0; nt < 8; nt++) {
        int col = wn * 64 + nt * 8 + quad * 2;
        bq[nt][0] = bias[col] + q[col];
        bq[nt][1] = bias[col + 1] + q[col + 1];
        vv[nt][0] = v[col];
        vv[nt][1] = v[col + 1];
    }

#pragma unroll
    for (int mt = 0; mt < 2; mt++) {
        float lo = 0.f, hi = 0.f;
#pragma unroll
        for (int nt = 0; nt < 8; nt++) {
            lo += fast_tanh(acc[mt][nt][0] + bq[nt][0]) * vv[nt][0];
            lo += fast_tanh(acc[mt][nt][1] + bq[nt][1]) * vv[nt][1];
            hi += fast_tanh(acc[mt][nt][2] + bq[nt][0]) * vv[nt][0];
            hi += fast_tanh(acc[mt][nt][3] + bq[nt][1]) * vv[nt][1];
        }
        lo += __shfl_xor_sync(0xffffffffu, lo, 1);
        lo += __shfl_xor_sync(0xffffffffu, lo, 2);
        hi += __shfl_xor_sync(0xffffffffu, hi, 1);
        hi += __shfl_xor_sync(0xffffffffu, hi, 2);
        if (quad == 0) {
            red[wm * 32 + mt * 16 + gid][wn]     = lo;
            red[wm * 32 + mt * 16 + gid + 8][wn] = hi;
        }
    }
    __syncthreads();

    if (tid < 64) {
        float t = red[tid][0] + red[tid][1] + red[tid][2] + red[tid][3];
        int r = rbase + tid;
        if (out) out[r] = t - (float)mask[r] * NEGV;
        else     g_scores[r] = t;
    }
}

// ---------------------------------------------------------------------------
// Softmax prep: per batch, masked max + exp + sum.
// ---------------------------------------------------------------------------
__global__ void softmax_prep_kernel(const int* __restrict__ mask) {
    int b = blockIdx.x;
    int tid = threadIdx.x;
    __shared__ float e[SS];
    __shared__ float red[256];

    float lm = -INFINITY;
#pragma unroll
    for (int i = 0; i < 4; i++) {
        int s = tid + i * 256;
        float val = g_scores[b * SS + s] - (float)mask[b * SS + s] * NEGV;
        e[s] = val;
        lm = fmaxf(lm, val);
    }
    red[tid] = lm;
    __syncthreads();
    for (int o = 128; o; o >>= 1) {
        if (tid < o) red[tid] = fmaxf(red[tid], red[tid + o]);
        __syncthreads();
    }
    float mx = red[0];
    __syncthreads();

    float ls = 0.f;
#pragma unroll
    for (int i = 0; i < 4; i++) {
        int s = tid + i * 256;
        float ev = expf(e[s] - mx);
        g_e[b * SS + s] = ev;
        ls += ev;
    }
    red[tid] = ls;
    __syncthreads();
    for (int o = 128; o; o >>= 1) {
        if (tid < o) red[tid] += red[tid + o];
        __syncthreads();
    }
    if (tid == 0) g_inv[b] = 1.0f / red[0];
}

// ---------------------------------------------------------------------------
// Glimpse partial: grid (NSPLIT, BB).  Block reduces SCHUNK s-rows.
// ---------------------------------------------------------------------------
__global__ void glimpse_partial_kernel(const float* __restrict__ ref) {
    int split = blockIdx.x, b = blockIdx.y;
    int tid = threadIdx.x;
    int s0 = split * SCHUNK;
    __shared__ float es[SCHUNK];
    if (tid < SCHUNK) es[tid] = g_e[b * SS + s0 + tid];
    __syncthreads();

    const float* rb = ref + ((size_t)b * SS + s0) * HH;
    int d = tid;
    float a0 = 0.f, a1 = 0.f, a2 = 0.f, a3 = 0.f;
#pragma unroll 4
    for (int s = 0; s < SCHUNK; s += 4) {
        a0 += es[s]     * rb[(size_t)(s)     * HH + d];
        a1 += es[s + 1] * rb[(size_t)(s + 1) * HH + d];
        a2 += es[s + 2] * rb[(size_t)(s + 2) * HH + d];
        a3 += es[s + 3] * rb[(size_t)(s + 3) * HH + d];
    }
    g_part[b][split][d] = (a0 + a1) + (a2 + a3);
}

__global__ void glimpse_combine_kernel(const float* __restrict__ query) {
    int b = blockIdx.x;
    int d = threadIdx.x;
    float s = 0.f;
#pragma unroll
    for (int p = 0; p < NSPLIT; p++) s += g_part[b][p][d];
    g_glimpse[b * HH + d] = s * g_inv[b] + query[b * HH + d];
}

// ---------------------------------------------------------------------------
// Launch. Input order: ref, query, mask, wg, bg, wqg, vg, wp, bp, wqp, vp
// ---------------------------------------------------------------------------
extern "C" void kernel_launch(void* const* d_in, const int* in_sizes, int n_in,
                              void* d_out, int out_size) {
    const float* ref   = (const float*)d_in[0];
    const float* query = (const float*)d_in[1];
    const int*   mask  = (const int*)  d_in[2];
    const float* wg    = (const float*)d_in[3];
    const float* bg    = (const float*)d_in[4];
    const float* wqg   = (const float*)d_in[5];
    const float* vg    = (const float*)d_in[6];
    const float* wp    = (const float*)d_in[7];
    const float* bp    = (const float*)d_in[8];
    const float* wqp   = (const float*)d_in[9];
    const float* vp    = (const float*)d_in[10];
    float* out = (float*)d_out;

    cudaFuncSetAttribute(gemm_tanh_mma,
                         cudaFuncAttributeMaxDynamicSharedMemorySize,
                         GEMM_DSMEM);

    convert_w_kernel<<<64, 256>>>(wg, wp);
    qmat_kernel<<<dim3(BB, 4), 256>>>(query, wqg, 0);
    gemm_tanh_mma<<<RR / BM, 256, GEMM_DSMEM>>>(ref, bg, vg, mask, nullptr, 0);
    softmax_prep_kernel<<<BB, 256>>>(mask);
    glimpse_partial_kernel<<<dim3(NSPLIT, BB), 256>>>(ref);
    glimpse_combine_kernel<<<BB, HH>>>(query);
    qmat_kernel<<<dim3(BB, 4), 256>>>(nullptr, wqp, 1);
    gemm_tanh_mma<<<RR / BM, 256, GEMM_DSMEM>>>(ref, bp, vp, mask, out, 1);
}

// round 12
// speedup vs baseline: 4.6487x; 1.0299x over previous
#include <cuda_runtime.h>
#include <cuda_bf16.h>
#include <math.h>
#include <stdint.h>

// Problem constants
#define BB 128
#define SS 1024
#define HH 256
#define RR (BB*SS)
#define NEGV 1e9f
#define NSPLIT 16
#define SCHUNK (SS/NSPLIT)   // 64

// Scratch (device globals; no allocation allowed)
__device__ float g_scores[RR];
__device__ float g_e[RR];
__device__ float g_inv[BB];
__device__ float g_part[BB][NSPLIT][HH];
__device__ float g_qg[BB*HH];
__device__ float g_glimpse[BB*HH];
__device__ float g_qp[BB*HH];
__device__ unsigned char g_w8[2][HH*HH];          // e4m3 wg, wp
__device__ unsigned char g_ref8[(size_t)RR*HH];   // e4m3 ref (32 MB)

__device__ __forceinline__ float fast_tanh(float x) {
    float y;
    asm("tanh.approx.f32 %0, %1;" : "=f"(y) : "f"(x));
    return y;
}
__device__ __forceinline__ unsigned smem_u32(const void* p) {
    return (unsigned)__cvta_generic_to_shared(p);
}
#define CP_ASYNC16(dst, src) \
    asm volatile("cp.async.cg.shared.global [%0], [%1], 16;" :: "r"(dst), "l"(src))
#define CP_COMMIT() asm volatile("cp.async.commit_group;")
#define CP_WAIT0()  asm volatile("cp.async.wait_group 0;" ::: "memory")
#define CP_WAIT1()  asm volatile("cp.async.wait_group 1;" ::: "memory")

#define LDMX4(r0, r1, r2, r3, addr) \
    asm volatile("ldmatrix.sync.aligned.m8n8.x4.b16 {%0,%1,%2,%3}, [%4];" \
                 : "=r"(r0), "=r"(r1), "=r"(r2), "=r"(r3) : "r"(addr))

// Pack 4 consecutive floats (k order) into 4 e4m3 bytes (byte0 = first k).
__device__ __forceinline__ unsigned pack_e4m3x4(float f0, float f1, float f2, float f3) {
    unsigned short lo, hi;
    asm("cvt.rn.satfinite.e4m3x2.f32 %0, %1, %2;" : "=h"(lo) : "f"(f1), "f"(f0));
    asm("cvt.rn.satfinite.e4m3x2.f32 %0, %1, %2;" : "=h"(hi) : "f"(f3), "f"(f2));
    return (unsigned)lo | ((unsigned)hi << 16);
}

// ---------------------------------------------------------------------------
// Convert wg, wp to e4m3 once per launch.
// ---------------------------------------------------------------------------
__global__ void convert_w_kernel(const float* __restrict__ wg,
                                 const float* __restrict__ wp) {
    int i = blockIdx.x * blockDim.x + threadIdx.x;   // float4 index
    float4 a = ((const float4*)wg)[i];
    float4 b = ((const float4*)wp)[i];
    ((unsigned*)g_w8[0])[i] = pack_e4m3x4(a.x, a.y, a.z, a.w);
    ((unsigned*)g_w8[1])[i] = pack_e4m3x4(b.x, b.y, b.z, b.w);
}

// ---------------------------------------------------------------------------
// Convert ref to e4m3 once per launch. 16 floats -> 16 bytes per thread.
// ---------------------------------------------------------------------------
__global__ void convert_ref_kernel(const float* __restrict__ ref) {
    size_t i = (size_t)blockIdx.x * blockDim.x + threadIdx.x;  // uint4 out index
    const float4* src = (const float4*)ref + i * 4;
    float4 p0 = src[0], p1 = src[1], p2 = src[2], p3 = src[3];
    uint4 o;
    o.x = pack_e4m3x4(p0.x, p0.y, p0.z, p0.w);
    o.y = pack_e4m3x4(p1.x, p1.y, p1.z, p1.w);
    o.z = pack_e4m3x4(p2.x, p2.y, p2.z, p2.w);
    o.w = pack_e4m3x4(p3.x, p3.y, p3.z, p3.w);
    ((uint4*)g_ref8)[i] = o;
}

// ---------------------------------------------------------------------------
// q[b,h] = sum_d in[b,d] * W[h,d]  (fp32, tiny).
// ---------------------------------------------------------------------------
__global__ void qmat_kernel(const float* __restrict__ inp,
                            const float* __restrict__ W, int dst) {
    int b = blockIdx.x;
    int tid = threadIdx.x;
    __shared__ float qs[HH];
    const float* src = inp ? inp : g_glimpse;
    qs[tid] = src[b * HH + tid];
    __syncthreads();

    int warp = tid >> 5, lane = tid & 31;
    float* outp = (dst ? g_qp : g_qg) + b * HH;
    int hbase = blockIdx.y * 64 + warp * 8;
#pragma unroll
    for (int hh = 0; hh < 8; hh++) {
        int h = hbase + hh;
        const float* wrow = W + h * HH;
        float s = 0.f;
#pragma unroll
        for (int i = 0; i < 8; i++) s += qs[lane + 32 * i] * wrow[lane + 32 * i];
#pragma unroll
        for (int o = 16; o; o >>= 1) s += __shfl_xor_sync(0xffffffffu, s, o);
        if (lane == 0) outp[h] = s;
    }
}

// ---------------------------------------------------------------------------
// Fused FP8 tensor-core GEMM + tanh + dot(v) reduce, 3-stage cp.async pipe.
// scores[r] = sum_h tanh( (ref[r,:] . W[h,:]) + bias[h] + q[b,h] ) * v[h]
// Tile BM=64 x BN=256 (all h), BK=64 bytes.  256 threads = 8 warps (2m x 4n).
// A and W both e4m3 in global; fragments via ldmatrix.x4.
// ---------------------------------------------------------------------------
#define BM 64
#define BKB 64              // K bytes per chunk
#define NCH (HH/BKB)        // 4
#define WSTB 80             // smem byte stride per row (64 + 16 pad)
#define ST_A (BM*WSTB)      // 5120
#define ST_W (HH*WSTB)      // 20480
#define ST_BYTES (ST_A + ST_W)       // 25600
#define GEMM_DSMEM (3*ST_BYTES)      // 76800

extern __shared__ unsigned char dyn8[];

__global__ __launch_bounds__(256, 2) void gemm_tanh_mma(
    const float* __restrict__ bias, const float* __restrict__ v,
    const int* __restrict__ mask, float* __restrict__ out, int sel)
{
    __shared__ float red[64][5];

    int tid = threadIdx.x;
    int warp = tid >> 5, lane = tid & 31;
    int wm = warp & 1, wn = warp >> 1;
    int gid = lane >> 2, quad = lane & 3;
    int rbase = blockIdx.x * BM;
    int b = rbase >> 10;

    const unsigned char* W8 = g_w8[sel];
    const unsigned char* A8 = g_ref8 + (size_t)rbase * HH;
    unsigned smem_base = smem_u32(dyn8);

    // cp.async coords
    int arow = tid >> 2, aseg = tid & 3;     // A: 64 rows x 4 16B segs

    float acc[2][8][4];
#pragma unroll
    for (int mt = 0; mt < 2; mt++)
#pragma unroll
        for (int nt = 0; nt < 8; nt++)
#pragma unroll
            for (int k = 0; k < 4; k++) acc[mt][nt][k] = 0.f;

    // ---- issue chunk (c) into stage (st) ----
    auto issue = [&](int c, int st) {
        unsigned abase = smem_base + st * ST_BYTES;
        unsigned wbase = abase + ST_A;
        CP_ASYNC16(abase + arow * WSTB + aseg * 16,
                   A8 + (size_t)arow * HH + c * BKB + aseg * 16);
#pragma unroll
        for (int i = 0; i < 4; i++) {
            int u = tid + i * 256;
            int row = u >> 2, seg = u & 3;
            CP_ASYNC16(wbase + row * WSTB + seg * 16,
                       W8 + (size_t)row * HH + c * BKB + seg * 16);
        }
        CP_COMMIT();
    };

    issue(0, 0);
    issue(1, 1);

    // ldmatrix lane coords
    int row16 = lane & 15, khalf = lane >> 4;       // A
    int g8 = lane >> 3, r8 = lane & 7;              // B

#pragma unroll
    for (int c = 0; c < NCH; c++) {
        int st = c % 3;
        if (c < NCH - 1) { CP_WAIT1(); } else { CP_WAIT0(); }
        __syncthreads();
        if (c + 2 < NCH) issue(c + 2, (c + 2) % 3);

        unsigned abase = smem_base + st * ST_BYTES;
        unsigned wbase = abase + ST_A;

#pragma unroll
        for (int ks = 0; ks < 2; ks++) {
            unsigned a[2][4];
#pragma unroll
            for (int mt = 0; mt < 2; mt++) {
                unsigned addr = abase + (wm * 32 + mt * 16 + row16) * WSTB
                              + ks * 32 + khalf * 16;
                LDMX4(a[mt][0], a[mt][1], a[mt][2], a[mt][3], addr);
            }
            unsigned bfr[8][2];
#pragma unroll
            for (int ntp = 0; ntp < 4; ntp++) {
                int nrow = wn * 64 + ntp * 16 + ((g8 >> 1) & 1) * 8 + r8;
                unsigned addr = wbase + nrow * WSTB + ks * 32 + (g8 & 1) * 16;
                LDMX4(bfr[2*ntp][0], bfr[2*ntp][1],
                      bfr[2*ntp+1][0], bfr[2*ntp+1][1], addr);
            }
#pragma unroll
            for (int nt = 0; nt < 8; nt++) {
#pragma unroll
                for (int mt = 0; mt < 2; mt++) {
                    asm volatile(
                        "mma.sync.aligned.m16n8k32.row.col.f32.e4m3.e4m3.f32 "
                        "{%0,%1,%2,%3}, {%4,%5,%6,%7}, {%8,%9}, {%0,%1,%2,%3};"
                        : "+f"(acc[mt][nt][0]), "+f"(acc[mt][nt][1]),
                          "+f"(acc[mt][nt][2]), "+f"(acc[mt][nt][3])
                        : "r"(a[mt][0]), "r"(a[mt][1]), "r"(a[mt][2]), "r"(a[mt][3]),
                          "r"(bfr[nt][0]), "r"(bfr[nt][1]));
                }
            }
        }
        if (c < NCH - 1) __syncthreads();
    }

    // Epilogue: bias + q, tanh, dot v, reduce.
    const float* q = (sel ? g_qp : g_qg) + b * HH;
    float bq[8][2], vv[8][2];
#pragma unroll
    for (int nt = 0; nt < 8; nt++) {
        int col = wn * 64 + nt * 8 + quad * 2;
        bq[nt][0] = bias[col] + q[col];
        bq[nt][1] = bias[col + 1] + q[col + 1];
        vv[nt][0] = v[col];
        vv[nt][1] = v[col + 1];
    }

#pragma unroll
    for (int mt = 0; mt < 2; mt++) {
        float lo = 0.f, hi = 0.f;
#pragma unroll
        for (int nt = 0; nt < 8; nt++) {
            lo += fast_tanh(acc[mt][nt][0] + bq[nt][0]) * vv[nt][0];
            lo += fast_tanh(acc[mt][nt][1] + bq[nt][1]) * vv[nt][1];
            hi += fast_tanh(acc[mt][nt][2] + bq[nt][0]) * vv[nt][0];
            hi += fast_tanh(acc[mt][nt][3] + bq[nt][1]) * vv[nt][1];
        }
        lo += __shfl_xor_sync(0xffffffffu, lo, 1);
        lo += __shfl_xor_sync(0xffffffffu, lo, 2);
        hi += __shfl_xor_sync(0xffffffffu, hi, 1);
        hi += __shfl_xor_sync(0xffffffffu, hi, 2);
        if (quad == 0) {
            red[wm * 32 + mt * 16 + gid][wn]     = lo;
            red[wm * 32 + mt * 16 + gid + 8][wn] = hi;
        }
    }
    __syncthreads();

    if (tid < 64) {
        float t = red[tid][0] + red[tid][1] + red[tid][2] + red[tid][3];
        int r = rbase + tid;
        if (out) out[r] = t - (float)mask[r] * NEGV;
        else     g_scores[r] = t;
    }
}

// ---------------------------------------------------------------------------
// Softmax prep: per batch, masked max + exp + sum.
// ---------------------------------------------------------------------------
__global__ void softmax_prep_kernel(const int* __restrict__ mask) {
    int b = blockIdx.x;
    int tid = threadIdx.x;
    __shared__ float e[SS];
    __shared__ float red[256];

    float lm = -INFINITY;
#pragma unroll
    for (int i = 0; i < 4; i++) {
        int s = tid + i * 256;
        float val = g_scores[b * SS + s] - (float)mask[b * SS + s] * NEGV;
        e[s] = val;
        lm = fmaxf(lm, val);
    }
    red[tid] = lm;
    __syncthreads();
    for (int o = 128; o; o >>= 1) {
        if (tid < o) red[tid] = fmaxf(red[tid], red[tid + o]);
        __syncthreads();
    }
    float mx = red[0];
    __syncthreads();

    float ls = 0.f;
#pragma unroll
    for (int i = 0; i < 4; i++) {
        int s = tid + i * 256;
        float ev = expf(e[s] - mx);
        g_e[b * SS + s] = ev;
        ls += ev;
    }
    red[tid] = ls;
    __syncthreads();
    for (int o = 128; o; o >>= 1) {
        if (tid < o) red[tid] += red[tid + o];
        __syncthreads();
    }
    if (tid == 0) g_inv[b] = 1.0f / red[0];
}

// ---------------------------------------------------------------------------
// Glimpse partial: grid (NSPLIT, BB).  Block reduces SCHUNK s-rows (fp32 ref).
// ---------------------------------------------------------------------------
__global__ void glimpse_partial_kernel(const float* __restrict__ ref) {
    int split = blockIdx.x, b = blockIdx.y;
    int tid = threadIdx.x;
    int s0 = split * SCHUNK;
    __shared__ float es[SCHUNK];
    if (tid < SCHUNK) es[tid] = g_e[b * SS + s0 + tid];
    __syncthreads();

    const float* rb = ref + ((size_t)b * SS + s0) * HH;
    int d = tid;
    float a0 = 0.f, a1 = 0.f, a2 = 0.f, a3 = 0.f;
#pragma unroll 4
    for (int s = 0; s < SCHUNK; s += 4) {
        a0 += es[s]     * rb[(size_t)(s)     * HH + d];
        a1 += es[s + 1] * rb[(size_t)(s + 1) * HH + d];
        a2 += es[s + 2] * rb[(size_t)(s + 2) * HH + d];
        a3 += es[s + 3] * rb[(size_t)(s + 3) * HH + d];
    }
    g_part[b][split][d] = (a0 + a1) + (a2 + a3);
}

__global__ void glimpse_combine_kernel(const float* __restrict__ query) {
    int b = blockIdx.x;
    int d = threadIdx.x;
    float s = 0.f;
#pragma unroll
    for (int p = 0; p < NSPLIT; p++) s += g_part[b][p][d];
    g_glimpse[b * HH + d] = s * g_inv[b] + query[b * HH + d];
}

// ---------------------------------------------------------------------------
// Launch. Input order: ref, query, mask, wg, bg, wqg, vg, wp, bp, wqp, vp
// ---------------------------------------------------------------------------
extern "C" void kernel_launch(void* const* d_in, const int* in_sizes, int n_in,
                              void* d_out, int out_size) {
    const float* ref   = (const float*)d_in[0];
    const float* query = (const float*)d_in[1];
    const int*   mask  = (const int*)  d_in[2];
    const float* wg    = (const float*)d_in[3];
    const float* bg    = (const float*)d_in[4];
    const float* wqg   = (const float*)d_in[5];
    const float* vg    = (const float*)d_in[6];
    const float* wp    = (const float*)d_in[7];
    const float* bp    = (const float*)d_in[8];
    const float* wqp   = (const float*)d_in[9];
    const float* vp    = (const float*)d_in[10];
    float* out = (float*)d_out;

    cudaFuncSetAttribute(gemm_tanh_mma,
                         cudaFuncAttributeMaxDynamicSharedMemorySize,
                         GEMM_DSMEM);

    convert_w_kernel<<<64, 256>>>(wg, wp);
    convert_ref_kernel<<<RR*HH/16/256, 256>>>(ref);      // 8192 blocks
    qmat_kernel<<<dim3(BB, 4), 256>>>(query, wqg, 0);
    gemm_tanh_mma<<<RR / BM, 256, GEMM_DSMEM>>>(bg, vg, mask, nullptr, 0);
    softmax_prep_kernel<<<BB, 256>>>(mask);
    glimpse_partial_kernel<<<dim3(NSPLIT, BB), 256>>>(ref);
    glimpse_combine_kernel<<<BB, HH>>>(query);
    qmat_kernel<<<dim3(BB, 4), 256>>>(nullptr, wqp, 1);
    gemm_tanh_mma<<<RR / BM, 256, GEMM_DSMEM>>>(bp, vp, mask, out, 1);
}

// round 15
// speedup vs baseline: 4.9957x; 1.0746x over previous
#include <cuda_runtime.h>
#include <cuda_bf16.h>
#include <cuda_fp8.h>
#include <math.h>
#include <stdint.h>

// Problem constants
#define BB 128
#define SS 1024
#define HH 256
#define RR (BB*SS)
#define NEGV 1e9f
#define NSPLIT 16
#define SCHUNK (SS/NSPLIT)   // 64

// Scratch (device globals; no allocation allowed)
__device__ float g_scores[RR];
__device__ float g_e[RR];
__device__ float g_inv[BB];
__device__ float g_part[BB][NSPLIT][HH];
__device__ float g_qg[BB*HH];
__device__ float g_glimpse[BB*HH];
__device__ float g_qp[BB*HH];
__device__ unsigned char g_w8[2][HH*HH];          // e4m3 wg, wp
__device__ unsigned char g_ref8[(size_t)RR*HH];   // e4m3 ref (32 MB), written by gemm1

__device__ __forceinline__ float fast_tanh(float x) {
    float y;
    asm("tanh.approx.f32 %0, %1;" : "=f"(y) : "f"(x));
    return y;
}
__device__ __forceinline__ unsigned smem_u32(const void* p) {
    return (unsigned)__cvta_generic_to_shared(p);
}
__device__ __forceinline__ float e4m3_f32(unsigned char x) {
    __half_raw h = __nv_cvt_fp8_to_halfraw(x, __NV_E4M3);
    return __half2float(*(__half*)&h);
}
#define CP_ASYNC16(dst, src) \
    asm volatile("cp.async.cg.shared.global [%0], [%1], 16;" :: "r"(dst), "l"(src))
#define CP_COMMIT() asm volatile("cp.async.commit_group;")
#define CP_WAIT0()  asm volatile("cp.async.wait_group 0;" ::: "memory")
#define CP_WAIT1()  asm volatile("cp.async.wait_group 1;" ::: "memory")

#define LDMX4(r0, r1, r2, r3, addr) \
    asm volatile("ldmatrix.sync.aligned.m8n8.x4.b16 {%0,%1,%2,%3}, [%4];" \
                 : "=r"(r0), "=r"(r1), "=r"(r2), "=r"(r3) : "r"(addr))

// Pack 4 consecutive floats (k order) into 4 e4m3 bytes (byte0 = first k).
__device__ __forceinline__ unsigned pack_e4m3x4(float f0, float f1, float f2, float f3) {
    unsigned short lo, hi;
    asm("cvt.rn.satfinite.e4m3x2.f32 %0, %1, %2;" : "=h"(lo) : "f"(f1), "f"(f0));
    asm("cvt.rn.satfinite.e4m3x2.f32 %0, %1, %2;" : "=h"(hi) : "f"(f3), "f"(f2));
    return (unsigned)lo | ((unsigned)hi << 16);
}

// ---------------------------------------------------------------------------
// Convert wg, wp to e4m3 once per launch.
// ---------------------------------------------------------------------------
__global__ void convert_w_kernel(const float* __restrict__ wg,
                                 const float* __restrict__ wp) {
    int i = blockIdx.x * blockDim.x + threadIdx.x;   // float4 index
    float4 a = ((const float4*)wg)[i];
    float4 b = ((const float4*)wp)[i];
    ((unsigned*)g_w8[0])[i] = pack_e4m3x4(a.x, a.y, a.z, a.w);
    ((unsigned*)g_w8[1])[i] = pack_e4m3x4(b.x, b.y, b.z, b.w);
}

// ---------------------------------------------------------------------------
// q[b,h] = sum_d in[b,d] * W[h,d]  (fp32, tiny).
// ---------------------------------------------------------------------------
__global__ void qmat_kernel(const float* __restrict__ inp,
                            const float* __restrict__ W, int dst) {
    int b = blockIdx.x;
    int tid = threadIdx.x;
    __shared__ float qs[HH];
    const float* src = inp ? inp : g_glimpse;
    qs[tid] = src[b * HH + tid];
    __syncthreads();

    int warp = tid >> 5, lane = tid & 31;
    float* outp = (dst ? g_qp : g_qg) + b * HH;
    int hbase = blockIdx.y * 64 + warp * 8;
#pragma unroll
    for (int hh = 0; hh < 8; hh++) {
        int h = hbase + hh;
        const float* wrow = W + h * HH;
        float s = 0.f;
#pragma unroll
        for (int i = 0; i < 8; i++) s += qs[lane + 32 * i] * wrow[lane + 32 * i];
#pragma unroll
        for (int o = 16; o; o >>= 1) s += __shfl_xor_sync(0xffffffffu, s, o);
        if (lane == 0) outp[h] = s;
    }
}

// ---------------------------------------------------------------------------
// Fused FP8 tensor-core GEMM + tanh + dot(v) reduce, 3-stage cp.async pipe.
// scores[r] = sum_h tanh( (ref[r,:] . W[h,:]) + bias[h] + q[b,h] ) * v[h]
// Tile BM=64 x BN=256 (all h), BK=64 bytes.  256 threads = 8 warps (2m x 4n).
// CONV=1: A from fp32 ref (LDG prefetch + pack), also STG'd to g_ref8.
// CONV=0: A via cp.async from g_ref8.
// ---------------------------------------------------------------------------
#define BM 64
#define BKB 64              // K bytes per chunk
#define NCH (HH/BKB)        // 4
#define WSTB 80             // smem byte stride per row (64 + 16 pad)
#define ST_A (BM*WSTB)      // 5120
#define ST_W (HH*WSTB)      // 20480
#define ST_BYTES (ST_A + ST_W)       // 25600
#define GEMM_DSMEM (3*ST_BYTES)      // 76800

extern __shared__ unsigned char dyn8[];

template<int CONV>
__global__ void __launch_bounds__(256, 2) gemm_tanh_mma(
    const float* __restrict__ ref,
    const float* __restrict__ bias, const float* __restrict__ v,
    const int* __restrict__ mask, float* __restrict__ out, int sel)
{
    __shared__ float red[64][5];

    int tid = threadIdx.x;
    int warp = tid >> 5, lane = tid & 31;
    int wm = warp & 1, wn = warp >> 1;
    int gid = lane >> 2, quad = lane & 3;
    int rbase = blockIdx.x * BM;
    int b = rbase >> 10;

    const unsigned char* W8 = g_w8[sel];
    unsigned smem_base = smem_u32(dyn8);

    // A coords: 64 rows x 4 16B segs, one uint4 per thread per chunk.
    int arow = tid >> 2, aseg = tid & 3;
    const unsigned char* A8 = g_ref8 + (size_t)rbase * HH;          // CONV=0 src
    const float* Af = ref + (size_t)(rbase + arow) * HH + aseg * 16; // CONV=1 src
    uint4* A8w = (uint4*)(g_ref8 + (size_t)(rbase + arow) * HH + aseg * 16);

    float acc[2][8][4];
#pragma unroll
    for (int mt = 0; mt < 2; mt++)
#pragma unroll
        for (int nt = 0; nt < 8; nt++)
#pragma unroll
            for (int k = 0; k < 4; k++) acc[mt][nt][k] = 0.f;

    // ---- issue chunk (c) into stage (st): W always; A too when CONV=0 ----
    auto issue = [&](int c, int st) {
        unsigned abase = smem_base + st * ST_BYTES;
        unsigned wbase = abase + ST_A;
        if (!CONV) {
            CP_ASYNC16(abase + arow * WSTB + aseg * 16,
                       A8 + (size_t)arow * HH + c * BKB + aseg * 16);
        }
#pragma unroll
        for (int i = 0; i < 4; i++) {
            int u = tid + i * 256;
            int row = u >> 2, seg = u & 3;
            CP_ASYNC16(wbase + row * WSTB + seg * 16,
                       W8 + (size_t)row * HH + c * BKB + seg * 16);
        }
        CP_COMMIT();
    };

    float4 pre0, pre1, pre2, pre3;   // CONV prefetch (chunk c+1)
    if (CONV) {
        pre0 = *(const float4*)(Af);
        pre1 = *(const float4*)(Af + 4);
        pre2 = *(const float4*)(Af + 8);
        pre3 = *(const float4*)(Af + 12);
    }
    issue(0, 0);
    issue(1, 1);

    // ldmatrix lane coords
    int row16 = lane & 15, khalf = lane >> 4;       // A
    int g8 = lane >> 3, r8 = lane & 7;              // B

#pragma unroll
    for (int c = 0; c < NCH; c++) {
        int st = c % 3;
        unsigned abase = smem_base + st * ST_BYTES;
        unsigned wbase = abase + ST_A;

        if (c < NCH - 1) { CP_WAIT1(); } else { CP_WAIT0(); }
        if (CONV) {
            // convert this chunk, STS into stage, STG to g_ref8
            uint4 av;
            av.x = pack_e4m3x4(pre0.x, pre0.y, pre0.z, pre0.w);
            av.y = pack_e4m3x4(pre1.x, pre1.y, pre1.z, pre1.w);
            av.z = pack_e4m3x4(pre2.x, pre2.y, pre2.z, pre2.w);
            av.w = pack_e4m3x4(pre3.x, pre3.y, pre3.z, pre3.w);
            *(uint4*)(dyn8 + st * ST_BYTES + arow * WSTB + aseg * 16) = av;
            *(uint4*)((unsigned char*)A8w + c * BKB) = av;
        }
        __syncthreads();
        if (c + 2 < NCH) issue(c + 2, (c + 2) % 3);
        if (CONV && c + 1 < NCH) {
            int kn = (c + 1) * BKB;
            pre0 = *(const float4*)(Af + kn);
            pre1 = *(const float4*)(Af + kn + 4);
            pre2 = *(const float4*)(Af + kn + 8);
            pre3 = *(const float4*)(Af + kn + 12);
        }

#pragma unroll
        for (int ks = 0; ks < 2; ks++) {
            unsigned a[2][4];
#pragma unroll
            for (int mt = 0; mt < 2; mt++) {
                unsigned addr = abase + (wm * 32 + mt * 16 + row16) * WSTB
                              + ks * 32 + khalf * 16;
                LDMX4(a[mt][0], a[mt][1], a[mt][2], a[mt][3], addr);
            }
            unsigned bfr[8][2];
#pragma unroll
            for (int ntp = 0; ntp < 4; ntp++) {
                int nrow = wn * 64 + ntp * 16 + ((g8 >> 1) & 1) * 8 + r8;
                unsigned addr = wbase + nrow * WSTB + ks * 32 + (g8 & 1) * 16;
                LDMX4(bfr[2*ntp][0], bfr[2*ntp][1],
                      bfr[2*ntp+1][0], bfr[2*ntp+1][1], addr);
            }
#pragma unroll
            for (int nt = 0; nt < 8; nt++) {
#pragma unroll
                for (int mt = 0; mt < 2; mt++) {
                    asm volatile(
                        "mma.sync.aligned.m16n8k32.row.col.f32.e4m3.e4m3.f32 "
                        "{%0,%1,%2,%3}, {%4,%5,%6,%7}, {%8,%9}, {%0,%1,%2,%3};"
                        : "+f"(acc[mt][nt][0]), "+f"(acc[mt][nt][1]),
                          "+f"(acc[mt][nt][2]), "+f"(acc[mt][nt][3])
                        : "r"(a[mt][0]), "r"(a[mt][1]), "r"(a[mt][2]), "r"(a[mt][3]),
                          "r"(bfr[nt][0]), "r"(bfr[nt][1]));
                }
            }
        }
        // single sync per iteration: the next iteration's post-wait sync
        // protects the stage being overwritten (consumed at c-1).
    }

    // Epilogue: bias + q, tanh, dot v, reduce.
    const float* q = (sel ? g_qp : g_qg) + b * HH;
    float bq[8][2], vv[8][2];
#pragma unroll
    for (int nt = 0; nt < 8; nt++) {
        int col = wn * 64 + nt * 8 + quad * 2;
        bq[nt][0] = bias[col] + q[col];
        bq[nt][1] = bias[col + 1] + q[col + 1];
        vv[nt][0] = v[col];
        vv[nt][1] = v[col + 1];
    }

#pragma unroll
    for (int mt = 0; mt < 2; mt++) {
        float lo = 0.f, hi = 0.f;
#pragma unroll
        for (int nt = 0; nt < 8; nt++) {
            lo += fast_tanh(acc[mt][nt][0] + bq[nt][0]) * vv[nt][0];
            lo += fast_tanh(acc[mt][nt][1] + bq[nt][1]) * vv[nt][1];
            hi += fast_tanh(acc[mt][nt][2] + bq[nt][0]) * vv[nt][0];
            hi += fast_tanh(acc[mt][nt][3] + bq[nt][1]) * vv[nt][1];
        }
        lo += __shfl_xor_sync(0xffffffffu, lo, 1);
        lo += __shfl_xor_sync(0xffffffffu, lo, 2);
        hi += __shfl_xor_sync(0xffffffffu, hi, 1);
        hi += __shfl_xor_sync(0xffffffffu, hi, 2);
        if (quad == 0) {
            red[wm * 32 + mt * 16 + gid][wn]     = lo;
            red[wm * 32 + mt * 16 + gid + 8][wn] = hi;
        }
    }
    __syncthreads();

    if (tid < 64) {
        float t = red[tid][0] + red[tid][1] + red[tid][2] + red[tid][3];
        int r = rbase + tid;
        if (out) out[r] = t - (float)mask[r] * NEGV;
        else     g_scores[r] = t;
    }
}

// ---------------------------------------------------------------------------
// Softmax prep: per batch, masked max + exp + sum.
// ---------------------------------------------------------------------------
__global__ void softmax_prep_kernel(const int* __restrict__ mask) {
    int b = blockIdx.x;
    int tid = threadIdx.x;
    __shared__ float e[SS];
    __shared__ float red[256];

    float lm = -INFINITY;
#pragma unroll
    for (int i = 0; i < 4; i++) {
        int s = tid + i * 256;
        float val = g_scores[b * SS + s] - (float)mask[b * SS + s] * NEGV;
        e[s] = val;
        lm = fmaxf(lm, val);
    }
    red[tid] = lm;
    __syncthreads();
    for (int o = 128; o; o >>= 1) {
        if (tid < o) red[tid] = fmaxf(red[tid], red[tid + o]);
        __syncthreads();
    }
    float mx = red[0];
    __syncthreads();

    float ls = 0.f;
#pragma unroll
    for (int i = 0; i < 4; i++) {
        int s = tid + i * 256;
        float ev = expf(e[s] - mx);
        g_e[b * SS + s] = ev;
        ls += ev;
    }
    red[tid] = ls;
    __syncthreads();
    for (int o = 128; o; o >>= 1) {
        if (tid < o) red[tid] += red[tid + o];
        __syncthreads();
    }
    if (tid == 0) g_inv[b] = 1.0f / red[0];
}

// ---------------------------------------------------------------------------
// Glimpse partial from fp8 ref: grid (NSPLIT, BB).
// ---------------------------------------------------------------------------
__global__ void glimpse_partial_kernel() {
    int split = blockIdx.x, b = blockIdx.y;
    int tid = threadIdx.x;
    int s0 = split * SCHUNK;
    __shared__ float es[SCHUNK];
    if (tid < SCHUNK) es[tid] = g_e[b * SS + s0 + tid];
    __syncthreads();

    const unsigned char* rb = g_ref8 + ((size_t)b * SS + s0) * HH;
    int d = tid;
    float a0 = 0.f, a1 = 0.f, a2 = 0.f, a3 = 0.f;
#pragma unroll 4
    for (int s = 0; s < SCHUNK; s += 4) {
        a0 += es[s]     * e4m3_f32(rb[(size_t)(s)     * HH + d]);
        a1 += es[s + 1] * e4m3_f32(rb[(size_t)(s + 1) * HH + d]);
        a2 += es[s + 2] * e4m3_f32(rb[(size_t)(s + 2) * HH + d]);
        a3 += es[s + 3] * e4m3_f32(rb[(size_t)(s + 3) * HH + d]);
    }
    g_part[b][split][d] = (a0 + a1) + (a2 + a3);
}

__global__ void glimpse_combine_kernel(const float* __restrict__ query) {
    int b = blockIdx.x;
    int d = threadIdx.x;
    float s = 0.f;
#pragma unroll
    for (int p = 0; p < NSPLIT; p++) s += g_part[b][p][d];
    g_glimpse[b * HH + d] = s * g_inv[b] + query[b * HH + d];
}

// ---------------------------------------------------------------------------
// Launch. Input order: ref, query, mask, wg, bg, wqg, vg, wp, bp, wqp, vp
// ---------------------------------------------------------------------------
extern "C" void kernel_launch(void* const* d_in, const int* in_sizes, int n_in,
                              void* d_out, int out_size) {
    const float* ref   = (const float*)d_in[0];
    const float* query = (const float*)d_in[1];
    const int*   mask  = (const int*)  d_in[2];
    const float* wg    = (const float*)d_in[3];
    const float* bg    = (const float*)d_in[4];
    const float* wqg   = (const float*)d_in[5];
    const float* vg    = (const float*)d_in[6];
    const float* wp    = (const float*)d_in[7];
    const float* bp    = (const float*)d_in[8];
    const float* wqp   = (const float*)d_in[9];
    const float* vp    = (const float*)d_in[10];
    float* out = (float*)d_out;

    cudaFuncSetAttribute(gemm_tanh_mma<1>,
                         cudaFuncAttributeMaxDynamicSharedMemorySize,
                         GEMM_DSMEM);
    cudaFuncSetAttribute(gemm_tanh_mma<0>,
                         cudaFuncAttributeMaxDynamicSharedMemorySize,
                         GEMM_DSMEM);

    convert_w_kernel<<<64, 256>>>(wg, wp);
    qmat_kernel<<<dim3(BB, 4), 256>>>(query, wqg, 0);
    // gemm1: fp32 A path, converts + persists fp8 ref for downstream
    gemm_tanh_mma<1><<<RR / BM, 256, GEMM_DSMEM>>>(ref, bg, vg, mask, nullptr, 0);
    softmax_prep_kernel<<<BB, 256>>>(mask);
    glimpse_partial_kernel<<<dim3(NSPLIT, BB), 256>>>();
    glimpse_combine_kernel<<<BB, HH>>>(query);
    qmat_kernel<<<dim3(BB, 4), 256>>>(nullptr, wqp, 1);
    // gemm2: fp8 A via cp.async
    gemm_tanh_mma<0><<<RR / BM, 256, GEMM_DSMEM>>>(ref, bp, vp, mask, out, 1);
}